// round 1
// baseline (speedup 1.0000x reference)
#include <cuda_runtime.h>
#include <math.h>

#define NN   50000
#define EE   100000
#define GG   2048
#define DD   32
#define FN   11
#define FE   4

// ---------------- device scratch (no allocations allowed) ----------------
__device__ float g_h[NN * DD];        // node state (out == h always)
__device__ float g_aggr[NN * DD];     // per-round message aggregate
__device__ float g_Y[NN * 5 * DD];    // per-node transformed vectors (4 edge-feat mats + bias mat)
__device__ float g_pool[GG * DD];     // per-graph sums
__device__ float g_cnt[GG];           // per-graph node counts

#define FULL 0xffffffffu

// ---------------- K0: out = relu(x @ lin0_w^T + lin0_b); h = out ----------------
__global__ void k_init(const float* __restrict__ x,
                       const float* __restrict__ w,   // [32,11]
                       const float* __restrict__ b) { // [32]
    __shared__ float ws[DD * FN];
    __shared__ float bs[DD];
    int t = threadIdx.x;
    for (int i = t; i < DD * FN; i += blockDim.x) ws[i] = w[i];
    if (t < DD) bs[t] = b[t];
    __syncthreads();
    int n = blockIdx.x * blockDim.x + t;
    if (n >= NN) return;
    float xv[FN];
#pragma unroll
    for (int f = 0; f < FN; f++) xv[f] = x[n * FN + f];
#pragma unroll
    for (int o = 0; o < DD; o++) {
        float s = bs[o];
#pragma unroll
        for (int f = 0; f < FN; f++) s += xv[f] * ws[o * FN + f];
        g_h[n * DD + o] = fmaxf(s, 0.0f);
    }
}

// ---------------- K1: Y[n,j,:] = h[n] @ M_j  (j=0..3 edge-feat mats, j=4 bias mat);
//                  also zeroes g_aggr for this round ----------------
__global__ void k_msgprep(const float* __restrict__ nn_w,   // [1024,4]
                          const float* __restrict__ nn_b) { // [1024]
    __shared__ float M[5][DD][DD];  // [j][i][o]
    int t = threadIdx.x;
    for (int idx = t; idx < DD * DD; idx += blockDim.x) {
        int i = idx / DD, o = idx % DD;
#pragma unroll
        for (int j = 0; j < 4; j++) M[j][i][o] = nn_w[idx * FE + j];
        M[4][i][o] = nn_b[idx];
    }
    __syncthreads();
    int gt   = blockIdx.x * blockDim.x + t;
    int n    = gt >> 5;
    int lane = gt & 31;
    if (n >= NN) return;
    float hv = g_h[n * DD + lane];
    g_aggr[n * DD + lane] = 0.0f;
    float y0 = 0.f, y1 = 0.f, y2 = 0.f, y3 = 0.f, y4 = 0.f;
#pragma unroll
    for (int i = 0; i < DD; i++) {
        float hi = __shfl_sync(FULL, hv, i);
        y0 += hi * M[0][i][lane];
        y1 += hi * M[1][i][lane];
        y2 += hi * M[2][i][lane];
        y3 += hi * M[3][i][lane];
        y4 += hi * M[4][i][lane];
    }
    float* yb = &g_Y[n * (5 * DD)];
    yb[0 * DD + lane] = y0;
    yb[1 * DD + lane] = y1;
    yb[2 * DD + lane] = y2;
    yb[3 * DD + lane] = y3;
    yb[4 * DD + lane] = y4;
}

// ---------------- K2: msg[e] = Y_b[src] + sum_f a_ef * Y_f[src]; scatter-add to dst ----------------
__global__ void k_edge(const int* __restrict__ ei,        // [2,E]
                       const float* __restrict__ ea) {    // [E,4]
    int gt   = blockIdx.x * blockDim.x + threadIdx.x;
    int e    = gt >> 5;
    int lane = gt & 31;
    if (e >= EE) return;
    int s = ei[e];
    int d = ei[EE + e];
    float4 a = reinterpret_cast<const float4*>(ea)[e];
    const float* yb = &g_Y[(size_t)s * (5 * DD)];
    float msg = yb[4 * DD + lane]
              + a.x * yb[0 * DD + lane]
              + a.y * yb[1 * DD + lane]
              + a.z * yb[2 * DD + lane]
              + a.w * yb[3 * DD + lane];
    atomicAdd(&g_aggr[d * DD + lane], msg);
}

// ---------------- K3: m = relu(aggr + h @ root_w + conv_b); h = GRU(m, h) ----------------
__global__ void k_node(const float* __restrict__ root_w,  // [32,32], (h@root_w)[o]=sum_i h_i*rw[i*32+o]
                       const float* __restrict__ conv_b,  // [32]
                       const float* __restrict__ wi,      // [96,32]
                       const float* __restrict__ wh,      // [96,32]
                       const float* __restrict__ bi,      // [96]
                       const float* __restrict__ bh) {    // [96]
    __shared__ float rw[DD * DD];       // as-is: rw[i*32+o]
    __shared__ float wiT[DD * 96];      // wiT[i*96+k] = wi[k*32+i]
    __shared__ float whT[DD * 96];
    __shared__ float cb[DD], bis[96], bhs[96];
    int t = threadIdx.x;
    for (int i = t; i < DD * DD; i += blockDim.x) rw[i] = root_w[i];
    for (int idx = t; idx < 96 * DD; idx += blockDim.x) {
        int k = idx / DD, i = idx % DD;
        wiT[i * 96 + k] = wi[idx];
        whT[i * 96 + k] = wh[idx];
    }
    if (t < DD) cb[t] = conv_b[t];
    if (t < 96) { bis[t] = bi[t]; bhs[t] = bh[t]; }
    __syncthreads();
    int gt   = blockIdx.x * blockDim.x + t;
    int n    = gt >> 5;
    int lane = gt & 31;
    if (n >= NN) return;
    float h   = g_h[n * DD + lane];
    float acc = g_aggr[n * DD + lane] + cb[lane];
#pragma unroll
    for (int i = 0; i < DD; i++) {
        float hi = __shfl_sync(FULL, h, i);
        acc += hi * rw[i * DD + lane];
    }
    float m = fmaxf(acc, 0.0f);
    float g0 = bis[lane], g1 = bis[lane + 32], g2 = bis[lane + 64];
    float q0 = bhs[lane], q1 = bhs[lane + 32], q2 = bhs[lane + 64];
#pragma unroll
    for (int i = 0; i < DD; i++) {
        float mi = __shfl_sync(FULL, m, i);
        float hi = __shfl_sync(FULL, h, i);
        const float* wr = &wiT[i * 96];
        const float* qr = &whT[i * 96];
        g0 += mi * wr[lane];      q0 += hi * qr[lane];
        g1 += mi * wr[lane + 32]; q1 += hi * qr[lane + 32];
        g2 += mi * wr[lane + 64]; q2 += hi * qr[lane + 64];
    }
    float r  = 1.0f / (1.0f + __expf(-(g0 + q0)));
    float z  = 1.0f / (1.0f + __expf(-(g1 + q1)));
    float nn = tanhf(g2 + r * q2);
    g_h[n * DD + lane] = (1.0f - z) * nn + z * h;
}

// ---------------- zero pool accumulators ----------------
__global__ void k_zero_pool() {
    int i = blockIdx.x * blockDim.x + threadIdx.x;
    if (i < GG * DD) g_pool[i] = 0.0f;
    if (i < GG) g_cnt[i] = 0.0f;
}

// ---------------- K4: per-graph sum + count ----------------
__global__ void k_pool(const int* __restrict__ batch) {
    int gt   = blockIdx.x * blockDim.x + threadIdx.x;
    int n    = gt >> 5;
    int lane = gt & 31;
    if (n >= NN) return;
    int b = batch[n];
    atomicAdd(&g_pool[b * DD + lane], g_h[n * DD + lane]);
    if (lane == 0) atomicAdd(&g_cnt[b], 1.0f);
}

// ---------------- K5: logits + log_softmax ----------------
__global__ void k_final(const float* __restrict__ w,   // [2,32]
                        const float* __restrict__ b,   // [2]
                        float* __restrict__ out) {     // [G,2]
    int g = blockIdx.x * blockDim.x + threadIdx.x;
    if (g >= GG) return;
    float inv = 1.0f / fmaxf(g_cnt[g], 1.0f);
    float l0 = b[0], l1 = b[1];
#pragma unroll
    for (int d = 0; d < DD; d++) {
        float p = g_pool[g * DD + d] * inv;
        l0 += p * w[d];
        l1 += p * w[DD + d];
    }
    float mx  = fmaxf(l0, l1);
    float lse = mx + logf(__expf(l0 - mx) + __expf(l1 - mx));
    out[g * 2 + 0] = l0 - lse;
    out[g * 2 + 1] = l1 - lse;
}

// ---------------- launch ----------------
extern "C" void kernel_launch(void* const* d_in, const int* in_sizes, int n_in,
                              void* d_out, int out_size) {
    const float* x        = (const float*)d_in[0];
    const float* edge_attr= (const float*)d_in[1];
    const float* lin0_w   = (const float*)d_in[2];
    const float* lin0_b   = (const float*)d_in[3];
    const float* nn_w     = (const float*)d_in[4];
    const float* nn_b     = (const float*)d_in[5];
    const float* root_w   = (const float*)d_in[6];
    const float* conv_b   = (const float*)d_in[7];
    const float* gru_wi   = (const float*)d_in[8];
    const float* gru_wh   = (const float*)d_in[9];
    const float* gru_bi   = (const float*)d_in[10];
    const float* gru_bh   = (const float*)d_in[11];
    const float* lin1_w   = (const float*)d_in[12];
    const float* lin1_b   = (const float*)d_in[13];
    const int*   edge_idx = (const int*)d_in[14];
    const int*   batch    = (const int*)d_in[15];
    float* out = (float*)d_out;

    const int TPB = 256;
    const int nodeWarpBlocks = (NN * 32 + TPB - 1) / TPB;   // 6250
    const int edgeWarpBlocks = (EE * 32 + TPB - 1) / TPB;   // 12500

    k_zero_pool<<<(GG * DD + TPB - 1) / TPB, TPB>>>();
    k_init<<<(NN + TPB - 1) / TPB, TPB>>>(x, lin0_w, lin0_b);

    for (int round = 0; round < 3; round++) {
        k_msgprep<<<nodeWarpBlocks, TPB>>>(nn_w, nn_b);
        k_edge<<<edgeWarpBlocks, TPB>>>(edge_idx, edge_attr);
        k_node<<<nodeWarpBlocks, TPB>>>(root_w, conv_b, gru_wi, gru_wh, gru_bi, gru_bh);
    }

    k_pool<<<nodeWarpBlocks, TPB>>>(batch);
    k_final<<<(GG + TPB - 1) / TPB, TPB>>>(lin1_w, lin1_b, out);
}

// round 2
// speedup vs baseline: 2.8871x; 2.8871x over previous
#include <cuda_runtime.h>
#include <math.h>

#define NN   50000
#define EE   100000
#define GG   2048
#define DD   32

// ---------------- device scratch ----------------
__device__ float g_h[NN * DD];        // node state
__device__ float g_aggr[NN * DD];     // per-round message aggregate
__device__ float g_Y[NN * 5 * DD];    // per-node transformed vectors (4 feat mats + bias mat)
__device__ float g_pool[GG * DD];     // per-graph sums
__device__ float g_cnt[GG];           // per-graph node counts

// ---------------- K0: h = relu(x @ lin0_w^T + lin0_b) ----------------
__global__ void k_init(const float* __restrict__ x,
                       const float* __restrict__ w,   // [32,11]
                       const float* __restrict__ b) { // [32]
    __shared__ float ws[DD * 11];
    __shared__ float bs[DD];
    int t = threadIdx.x;
    for (int i = t; i < DD * 11; i += blockDim.x) ws[i] = w[i];
    if (t < DD) bs[t] = b[t];
    __syncthreads();
    int n = blockIdx.x * blockDim.x + t;
    if (n >= NN) return;
    float xv[11];
#pragma unroll
    for (int f = 0; f < 11; f++) xv[f] = x[n * 11 + f];
#pragma unroll
    for (int o = 0; o < DD; o++) {
        float s = bs[o];
#pragma unroll
        for (int f = 0; f < 11; f++) s += xv[f] * ws[o * 11 + f];
        g_h[n * DD + o] = fmaxf(s, 0.0f);
    }
}

// ---------------- K1: Y[n,j,:] = h[n] @ M_j ; zero aggr ----------------
// 8 warps/block, 8 nodes/warp -> 64 nodes/block. lane = output dim o.
__global__ void k_msgprep(const float* __restrict__ nn_w,   // [1024,4]
                          const float* __restrict__ nn_b) { // [1024]
    __shared__ __align__(16) float hs[64 * 32];
    __shared__ float Ms[5 * 32 * 32];   // Ms[j*1024 + i*32 + o]
    int t = threadIdx.x;
    for (int idx = t; idx < 1024; idx += 256) {
#pragma unroll
        for (int j = 0; j < 4; j++) Ms[j * 1024 + idx] = nn_w[idx * 4 + j];
        Ms[4 * 1024 + idx] = nn_b[idx];
    }
    int nbase = blockIdx.x * 64;
    for (int idx = t; idx < 2048; idx += 256) {
        int g = nbase * 32 + idx;
        hs[idx] = (g < NN * 32) ? g_h[g] : 0.0f;
    }
    __syncthreads();

    int w = t >> 5, lane = t & 31;
    int n0 = nbase + w * 8;
    const float* hrow = &hs[(w * 8) * 32];

    float y[8][5];
#pragma unroll
    for (int n = 0; n < 8; n++)
#pragma unroll
        for (int j = 0; j < 5; j++) y[n][j] = 0.0f;

#pragma unroll
    for (int i4 = 0; i4 < 8; i4++) {
        float wv[4][5];
#pragma unroll
        for (int ii = 0; ii < 4; ii++) {
            int i = i4 * 4 + ii;
#pragma unroll
            for (int j = 0; j < 5; j++) wv[ii][j] = Ms[j * 1024 + i * 32 + lane];
        }
#pragma unroll
        for (int n = 0; n < 8; n++) {
            float4 hv = *(const float4*)&hrow[n * 32 + i4 * 4];
#pragma unroll
            for (int j = 0; j < 5; j++)
                y[n][j] += hv.x * wv[0][j] + hv.y * wv[1][j]
                         + hv.z * wv[2][j] + hv.w * wv[3][j];
        }
    }
#pragma unroll
    for (int n = 0; n < 8; n++) {
        int node = n0 + n;
        if (node >= NN) break;
        float* yb = &g_Y[(size_t)node * 160];
#pragma unroll
        for (int j = 0; j < 5; j++) yb[j * 32 + lane] = y[n][j];
        g_aggr[node * 32 + lane] = 0.0f;
    }
}

// ---------------- K2: per-edge message + scatter-add ----------------
__global__ void k_edge(const int* __restrict__ ei,        // [2,E]
                       const float* __restrict__ ea) {    // [E,4]
    int gt   = blockIdx.x * blockDim.x + threadIdx.x;
    int e    = gt >> 5;
    int lane = gt & 31;
    if (e >= EE) return;
    int s = ei[e];
    int d = ei[EE + e];
    float4 a = reinterpret_cast<const float4*>(ea)[e];
    const float* yb = &g_Y[(size_t)s * 160];
    float msg = yb[4 * 32 + lane]
              + a.x * yb[0 * 32 + lane]
              + a.y * yb[1 * 32 + lane]
              + a.z * yb[2 * 32 + lane]
              + a.w * yb[3 * 32 + lane];
    atomicAdd(&g_aggr[d * 32 + lane], msg);
}

// ---------------- K3: m = relu(aggr + h@root_w + conv_b); h = GRU(m,h); opt pool ----------------
// 8 warps/block, 8 nodes/warp.
__global__ void k_node(const float* __restrict__ root_w,  // [32,32]
                       const float* __restrict__ conv_b,  // [32]
                       const float* __restrict__ wi,      // [96,32]
                       const float* __restrict__ wh,      // [96,32]
                       const float* __restrict__ bi,      // [96]
                       const float* __restrict__ bh,      // [96]
                       const int* __restrict__ batch,
                       int do_pool) {
    __shared__ __align__(16) float hs[64 * 32];
    __shared__ __align__(16) float ms[64 * 32];
    __shared__ float rw[32 * 32];
    __shared__ float wiT[32 * 96];      // wiT[i*96+k] = wi[k*32+i]
    __shared__ float whT[32 * 96];
    __shared__ float cb[32], bis[96], bhs[96];
    int t = threadIdx.x;
    int nbase = blockIdx.x * 64;
    for (int i = t; i < 1024; i += 256) rw[i] = root_w[i];
    for (int idx = t; idx < 96 * 32; idx += 256) {
        int k = idx >> 5, i = idx & 31;
        wiT[i * 96 + k] = wi[idx];
        whT[i * 96 + k] = wh[idx];
    }
    if (t < 32) cb[t] = conv_b[t];
    if (t < 96) { bis[t] = bi[t]; bhs[t] = bh[t]; }
    for (int idx = t; idx < 2048; idx += 256) {
        int g = nbase * 32 + idx;
        hs[idx] = (g < NN * 32) ? g_h[g] : 0.0f;
    }
    __syncthreads();

    int w = t >> 5, lane = t & 31;
    int n0 = nbase + w * 8;
    const float* hrow = &hs[(w * 8) * 32];
    float*       mrow = &ms[(w * 8) * 32];

    // --- root mat-vec: acc[n] = aggr + cb + h[n] @ root_w ---
    float acc[8];
#pragma unroll
    for (int n = 0; n < 8; n++) {
        int node = n0 + n;
        acc[n] = (node < NN) ? g_aggr[node * 32 + lane] + cb[lane] : 0.0f;
    }
#pragma unroll
    for (int i4 = 0; i4 < 8; i4++) {
        float wr[4];
#pragma unroll
        for (int ii = 0; ii < 4; ii++) wr[ii] = rw[(i4 * 4 + ii) * 32 + lane];
#pragma unroll
        for (int n = 0; n < 8; n++) {
            float4 hv = *(const float4*)&hrow[n * 32 + i4 * 4];
            acc[n] += hv.x * wr[0] + hv.y * wr[1] + hv.z * wr[2] + hv.w * wr[3];
        }
    }
#pragma unroll
    for (int n = 0; n < 8; n++) mrow[n * 32 + lane] = fmaxf(acc[n], 0.0f);
    __syncwarp();

    // --- GRU gates ---
    float G0[8], G1[8], G2[8], Q0[8], Q1[8], Q2[8];
#pragma unroll
    for (int n = 0; n < 8; n++) {
        G0[n] = bis[lane]; G1[n] = bis[lane + 32]; G2[n] = bis[lane + 64];
        Q0[n] = bhs[lane]; Q1[n] = bhs[lane + 32]; Q2[n] = bhs[lane + 64];
    }
#pragma unroll
    for (int i4 = 0; i4 < 8; i4++) {
        float a0[4], a1[4], a2[4], b0[4], b1[4], b2[4];
#pragma unroll
        for (int ii = 0; ii < 4; ii++) {
            int i = i4 * 4 + ii;
            a0[ii] = wiT[i * 96 + lane];
            a1[ii] = wiT[i * 96 + lane + 32];
            a2[ii] = wiT[i * 96 + lane + 64];
            b0[ii] = whT[i * 96 + lane];
            b1[ii] = whT[i * 96 + lane + 32];
            b2[ii] = whT[i * 96 + lane + 64];
        }
#pragma unroll
        for (int n = 0; n < 8; n++) {
            float4 mv = *(const float4*)&mrow[n * 32 + i4 * 4];
            float4 hv = *(const float4*)&hrow[n * 32 + i4 * 4];
            G0[n] += mv.x * a0[0] + mv.y * a0[1] + mv.z * a0[2] + mv.w * a0[3];
            G1[n] += mv.x * a1[0] + mv.y * a1[1] + mv.z * a1[2] + mv.w * a1[3];
            G2[n] += mv.x * a2[0] + mv.y * a2[1] + mv.z * a2[2] + mv.w * a2[3];
            Q0[n] += hv.x * b0[0] + hv.y * b0[1] + hv.z * b0[2] + hv.w * b0[3];
            Q1[n] += hv.x * b1[0] + hv.y * b1[1] + hv.z * b1[2] + hv.w * b1[3];
            Q2[n] += hv.x * b2[0] + hv.y * b2[1] + hv.z * b2[2] + hv.w * b2[3];
        }
    }

#pragma unroll
    for (int n = 0; n < 8; n++) {
        int node = n0 + n;
        if (node >= NN) break;
        float h  = hrow[n * 32 + lane];
        float r  = 1.0f / (1.0f + __expf(-(G0[n] + Q0[n])));
        float z  = 1.0f / (1.0f + __expf(-(G1[n] + Q1[n])));
        float nv = tanhf(G2[n] + r * Q2[n]);
        float hn = (1.0f - z) * nv + z * h;
        g_h[node * 32 + lane] = hn;
        if (do_pool) {
            int b = batch[node];
            atomicAdd(&g_pool[b * 32 + lane], hn);
            if (lane == 0) atomicAdd(&g_cnt[b], 1.0f);
        }
    }
}

// ---------------- zero pool accumulators ----------------
__global__ void k_zero_pool() {
    int i = blockIdx.x * blockDim.x + threadIdx.x;
    if (i < GG * DD) g_pool[i] = 0.0f;
    if (i < GG) g_cnt[i] = 0.0f;
}

// ---------------- K5: logits + log_softmax ----------------
__global__ void k_final(const float* __restrict__ w,   // [2,32]
                        const float* __restrict__ b,   // [2]
                        float* __restrict__ out) {     // [G,2]
    int g = blockIdx.x * blockDim.x + threadIdx.x;
    if (g >= GG) return;
    float inv = 1.0f / fmaxf(g_cnt[g], 1.0f);
    float l0 = b[0], l1 = b[1];
#pragma unroll
    for (int d = 0; d < DD; d++) {
        float p = g_pool[g * DD + d] * inv;
        l0 += p * w[d];
        l1 += p * w[DD + d];
    }
    float mx  = fmaxf(l0, l1);
    float lse = mx + logf(__expf(l0 - mx) + __expf(l1 - mx));
    out[g * 2 + 0] = l0 - lse;
    out[g * 2 + 1] = l1 - lse;
}

// ---------------- launch ----------------
extern "C" void kernel_launch(void* const* d_in, const int* in_sizes, int n_in,
                              void* d_out, int out_size) {
    const float* x        = (const float*)d_in[0];
    const float* edge_attr= (const float*)d_in[1];
    const float* lin0_w   = (const float*)d_in[2];
    const float* lin0_b   = (const float*)d_in[3];
    const float* nn_w     = (const float*)d_in[4];
    const float* nn_b     = (const float*)d_in[5];
    const float* root_w   = (const float*)d_in[6];
    const float* conv_b   = (const float*)d_in[7];
    const float* gru_wi   = (const float*)d_in[8];
    const float* gru_wh   = (const float*)d_in[9];
    const float* gru_bi   = (const float*)d_in[10];
    const float* gru_bh   = (const float*)d_in[11];
    const float* lin1_w   = (const float*)d_in[12];
    const float* lin1_b   = (const float*)d_in[13];
    const int*   edge_idx = (const int*)d_in[14];
    const int*   batch    = (const int*)d_in[15];
    float* out = (float*)d_out;

    const int TPB = 256;
    const int nodeBlocks = (NN + 63) / 64;                 // 782
    const int edgeWarpBlocks = (EE * 32 + TPB - 1) / TPB;  // 12500

    k_zero_pool<<<(GG * DD + TPB - 1) / TPB, TPB>>>();
    k_init<<<(NN + TPB - 1) / TPB, TPB>>>(x, lin0_w, lin0_b);

    for (int round = 0; round < 3; round++) {
        k_msgprep<<<nodeBlocks, TPB>>>(nn_w, nn_b);
        k_edge<<<edgeWarpBlocks, TPB>>>(edge_idx, edge_attr);
        k_node<<<nodeBlocks, TPB>>>(root_w, conv_b, gru_wi, gru_wh,
                                    gru_bi, gru_bh, batch, round == 2);
    }

    k_final<<<(GG + TPB - 1) / TPB, TPB>>>(lin1_w, lin1_b, out);
}

// round 3
// speedup vs baseline: 4.5803x; 1.5865x over previous
#include <cuda_runtime.h>
#include <math.h>

#define NN   50000
#define EE   100000
#define GG   2048
#define DD   32

typedef unsigned long long ull;

// ---------------- device scratch ----------------
__device__ float g_h[NN * DD];
__device__ float g_aggr[NN * DD];
__device__ float g_Y[NN * 5 * DD];
__device__ float g_pool[GG * DD];
__device__ float g_cnt[GG];

// packed (pair-over-i, per-lane duplicate-free) weights, built once per launch
__device__ ull P_MS2[5 * 16 * 32];   // (j, i2, o)
__device__ ull P_WI2[16 * 96];       // (i2, k) : wi[k*32+i]
__device__ ull P_WH2[16 * 96];
__device__ ull P_RW2[16 * 32];       // (i2, o) : root_w[i*32+o]

// ---------------- f32x2 helpers ----------------
__device__ __forceinline__ ull ffma2(ull a, ull b, ull c) {
    ull d;
    asm("fma.rn.f32x2 %0, %1, %2, %3;" : "=l"(d) : "l"(a), "l"(b), "l"(c));
    return d;
}
__device__ __forceinline__ float flo(ull v) { return __uint_as_float((unsigned)v); }
__device__ __forceinline__ float fhi(ull v) { return __uint_as_float((unsigned)(v >> 32)); }

// ---------------- K_pack: zero pool accumulators + build packed weights ----------------
__global__ void k_pack(const float* __restrict__ root_w,
                       const float* __restrict__ wi,
                       const float* __restrict__ wh,
                       const float* __restrict__ nn_w,
                       const float* __restrict__ nn_b) {
    int gid = blockIdx.x * blockDim.x + threadIdx.x;
    if (gid < GG * DD) g_pool[gid] = 0.0f;
    if (gid < GG) g_cnt[gid] = 0.0f;

    float* RWf = (float*)P_RW2;
    float* WIf = (float*)P_WI2;
    float* WHf = (float*)P_WH2;
    float* MSf = (float*)P_MS2;

    if (gid < 1024) {                        // root_w
        int i = gid >> 5, o = gid & 31;
        RWf[(((i >> 1) << 5) + o) * 2 + (i & 1)] = root_w[gid];
    } else if (gid < 1024 + 3072) {          // wi
        int idx = gid - 1024;
        int k = idx >> 5, i = idx & 31;
        WIf[(((i >> 1) * 96) + k) * 2 + (i & 1)] = wi[idx];
    } else if (gid < 1024 + 6144) {          // wh
        int idx = gid - 4096;
        int k = idx >> 5, i = idx & 31;
        WHf[(((i >> 1) * 96) + k) * 2 + (i & 1)] = wh[idx];
    } else if (gid < 1024 + 6144 + 5120) {   // nn_w / nn_b (5 matrices)
        int idx = gid - 7168;
        int j = idx >> 10, rem = idx & 1023;
        int i = rem >> 5, o = rem & 31;
        int d = (((i >> 1) << 5) + o) * 2 + (i & 1);
        MSf[j * 1024 + d] = (j < 4) ? nn_w[rem * 4 + j] : nn_b[rem];
    }
}

// ---------------- K_init: h0 = relu(lin0); Y0 = h0 @ M_j ; zero aggr ----------------
// 256 threads, 8 warps, 4 nodes/warp -> 32 nodes/block
__global__ __launch_bounds__(256) void k_init(const float* __restrict__ x,
                                              const float* __restrict__ w,   // [32,11]
                                              const float* __restrict__ b) { // [32]
    __shared__ __align__(16) float hs[32 * 32];
    int t = threadIdx.x, wrp = t >> 5, lane = t & 31;
    int n0 = blockIdx.x * 32 + wrp * 4;
    float* hrow = &hs[(wrp * 4) * 32];

    float bias = __ldg(&b[lane]);
    float wv[11];
#pragma unroll
    for (int f = 0; f < 11; f++) wv[f] = __ldg(&w[lane * 11 + f]);

    float hn[4];
#pragma unroll
    for (int n = 0; n < 4; n++) {
        int node = n0 + n;
        float s = bias;
        if (node < NN) {
#pragma unroll
            for (int f = 0; f < 11; f++) s += __ldg(&x[node * 11 + f]) * wv[f];
        }
        hn[n] = fmaxf(s, 0.0f);
        hrow[n * 32 + lane] = hn[n];
    }
    __syncwarp();

    ull y2[4][5];
#pragma unroll
    for (int n = 0; n < 4; n++)
#pragma unroll
        for (int j = 0; j < 5; j++) y2[n][j] = 0ull;

#pragma unroll
    for (int i2 = 0; i2 < 16; i2++) {
        ull mw[5];
#pragma unroll
        for (int j = 0; j < 5; j++) mw[j] = __ldg(&P_MS2[j * 512 + i2 * 32 + lane]);
#pragma unroll
        for (int n = 0; n < 4; n++) {
            ull h2 = *(const ull*)&hrow[n * 32 + i2 * 2];
#pragma unroll
            for (int j = 0; j < 5; j++) y2[n][j] = ffma2(h2, mw[j], y2[n][j]);
        }
    }
#pragma unroll
    for (int n = 0; n < 4; n++) {
        int node = n0 + n;
        if (node >= NN) break;
        g_h[node * 32 + lane] = hn[n];
        g_aggr[node * 32 + lane] = 0.0f;
        float* yb = &g_Y[(size_t)node * 160];
#pragma unroll
        for (int j = 0; j < 5; j++) yb[j * 32 + lane] = flo(y2[n][j]) + fhi(y2[n][j]);
    }
}

// ---------------- K_edge: per-edge message + scatter-add ----------------
__global__ void k_edge(const int* __restrict__ ei,        // [2,E]
                       const float* __restrict__ ea) {    // [E,4]
    int gt   = blockIdx.x * blockDim.x + threadIdx.x;
    int e    = gt >> 5;
    int lane = gt & 31;
    if (e >= EE) return;
    int s = __ldg(&ei[e]);
    int d = __ldg(&ei[EE + e]);
    float4 a = __ldg(&reinterpret_cast<const float4*>(ea)[e]);
    const float* yb = &g_Y[(size_t)s * 160];
    float msg = __ldg(&yb[4 * 32 + lane])
              + a.x * __ldg(&yb[0 * 32 + lane])
              + a.y * __ldg(&yb[1 * 32 + lane])
              + a.z * __ldg(&yb[2 * 32 + lane])
              + a.w * __ldg(&yb[3 * 32 + lane]);
    atomicAdd(&g_aggr[d * 32 + lane], msg);
}

// ---------------- K_node: NNConv-root + GRU, fused with next-round Y (or pooling) ----------------
// 256 threads, 8 warps, 4 nodes/warp -> 32 nodes/block
__global__ __launch_bounds__(256) void k_node(const float* __restrict__ conv_b, // [32]
                                              const float* __restrict__ bi,     // [96]
                                              const float* __restrict__ bh,     // [96]
                                              const int* __restrict__ batch,
                                              int last) {
    __shared__ __align__(16) float hs[32 * 32];
    __shared__ __align__(16) float ms[32 * 32];
    int t = threadIdx.x, wrp = t >> 5, lane = t & 31;
    int nbase = blockIdx.x * 32;
    int n0 = nbase + wrp * 4;
    float* hrow = &hs[(wrp * 4) * 32];
    float* mrow = &ms[(wrp * 4) * 32];

    // stage h for this warp's 4 nodes
#pragma unroll
    for (int n = 0; n < 4; n++) {
        int node = n0 + n;
        hrow[n * 32 + lane] = (node < NN) ? g_h[node * 32 + lane] : 0.0f;
    }
    __syncwarp();

    // --- root mat-vec ---
    ull acc2[4];
#pragma unroll
    for (int n = 0; n < 4; n++) acc2[n] = 0ull;
#pragma unroll
    for (int i2 = 0; i2 < 16; i2++) {
        ull wv = __ldg(&P_RW2[i2 * 32 + lane]);
#pragma unroll
        for (int n = 0; n < 4; n++) {
            ull h2 = *(const ull*)&hrow[n * 32 + i2 * 2];
            acc2[n] = ffma2(h2, wv, acc2[n]);
        }
    }
    float cb = __ldg(&conv_b[lane]);
#pragma unroll
    for (int n = 0; n < 4; n++) {
        int node = n0 + n;
        float a = 0.0f;
        if (node < NN) {
            a = g_aggr[node * 32 + lane];
            g_aggr[node * 32 + lane] = 0.0f;   // pre-zero for next round
        }
        mrow[n * 32 + lane] = fmaxf(flo(acc2[n]) + fhi(acc2[n]) + a + cb, 0.0f);
    }
    __syncwarp();

    // --- GRU gates ---
    ull G0[4], G1[4], G2[4], Q0[4], Q1[4], Q2[4];
#pragma unroll
    for (int n = 0; n < 4; n++) { G0[n]=G1[n]=G2[n]=Q0[n]=Q1[n]=Q2[n]=0ull; }
#pragma unroll
    for (int i2 = 0; i2 < 16; i2++) {
        ull a0 = __ldg(&P_WI2[i2 * 96 + lane]);
        ull a1 = __ldg(&P_WI2[i2 * 96 + lane + 32]);
        ull a2 = __ldg(&P_WI2[i2 * 96 + lane + 64]);
        ull b0 = __ldg(&P_WH2[i2 * 96 + lane]);
        ull b1 = __ldg(&P_WH2[i2 * 96 + lane + 32]);
        ull b2 = __ldg(&P_WH2[i2 * 96 + lane + 64]);
#pragma unroll
        for (int n = 0; n < 4; n++) {
            ull m2 = *(const ull*)&mrow[n * 32 + i2 * 2];
            ull h2 = *(const ull*)&hrow[n * 32 + i2 * 2];
            G0[n] = ffma2(m2, a0, G0[n]);
            G1[n] = ffma2(m2, a1, G1[n]);
            G2[n] = ffma2(m2, a2, G2[n]);
            Q0[n] = ffma2(h2, b0, Q0[n]);
            Q1[n] = ffma2(h2, b1, Q1[n]);
            Q2[n] = ffma2(h2, b2, Q2[n]);
        }
    }
    float bi0 = __ldg(&bi[lane]), bi1 = __ldg(&bi[lane + 32]), bi2 = __ldg(&bi[lane + 64]);
    float bh0 = __ldg(&bh[lane]), bh1 = __ldg(&bh[lane + 32]), bh2 = __ldg(&bh[lane + 64]);

    float hn[4];
#pragma unroll
    for (int n = 0; n < 4; n++) {
        float h  = hrow[n * 32 + lane];
        float g0 = flo(G0[n]) + fhi(G0[n]) + bi0;
        float g1 = flo(G1[n]) + fhi(G1[n]) + bi1;
        float g2 = flo(G2[n]) + fhi(G2[n]) + bi2;
        float q0 = flo(Q0[n]) + fhi(Q0[n]) + bh0;
        float q1 = flo(Q1[n]) + fhi(Q1[n]) + bh1;
        float q2 = flo(Q2[n]) + fhi(Q2[n]) + bh2;
        float r  = 1.0f / (1.0f + __expf(-(g0 + q0)));
        float z  = 1.0f / (1.0f + __expf(-(g1 + q1)));
        float nv = tanhf(g2 + r * q2);
        hn[n] = (1.0f - z) * nv + z * h;
    }

    if (last) {
#pragma unroll
        for (int n = 0; n < 4; n++) {
            int node = n0 + n;
            if (node >= NN) break;
            int bg = __ldg(&batch[node]);
            atomicAdd(&g_pool[bg * 32 + lane], hn[n]);
            if (lane == 0) atomicAdd(&g_cnt[bg], 1.0f);
        }
        return;
    }

    // --- fused Y for next round: overwrite hs with hn, then Y = hn @ M_j ---
#pragma unroll
    for (int n = 0; n < 4; n++) hrow[n * 32 + lane] = hn[n];
    __syncwarp();

    ull y2[4][5];
#pragma unroll
    for (int n = 0; n < 4; n++)
#pragma unroll
        for (int j = 0; j < 5; j++) y2[n][j] = 0ull;
#pragma unroll
    for (int i2 = 0; i2 < 16; i2++) {
        ull mw[5];
#pragma unroll
        for (int j = 0; j < 5; j++) mw[j] = __ldg(&P_MS2[j * 512 + i2 * 32 + lane]);
#pragma unroll
        for (int n = 0; n < 4; n++) {
            ull h2 = *(const ull*)&hrow[n * 32 + i2 * 2];
#pragma unroll
            for (int j = 0; j < 5; j++) y2[n][j] = ffma2(h2, mw[j], y2[n][j]);
        }
    }
#pragma unroll
    for (int n = 0; n < 4; n++) {
        int node = n0 + n;
        if (node >= NN) break;
        g_h[node * 32 + lane] = hn[n];
        float* yb = &g_Y[(size_t)node * 160];
#pragma unroll
        for (int j = 0; j < 5; j++) yb[j * 32 + lane] = flo(y2[n][j]) + fhi(y2[n][j]);
    }
}

// ---------------- K_final: logits + log_softmax ----------------
__global__ void k_final(const float* __restrict__ w,   // [2,32]
                        const float* __restrict__ b,   // [2]
                        float* __restrict__ out) {     // [G,2]
    int g = blockIdx.x * blockDim.x + threadIdx.x;
    if (g >= GG) return;
    float inv = 1.0f / fmaxf(g_cnt[g], 1.0f);
    float l0 = b[0], l1 = b[1];
#pragma unroll
    for (int d = 0; d < DD; d++) {
        float p = g_pool[g * DD + d] * inv;
        l0 += p * w[d];
        l1 += p * w[DD + d];
    }
    float mx  = fmaxf(l0, l1);
    float lse = mx + logf(__expf(l0 - mx) + __expf(l1 - mx));
    out[g * 2 + 0] = l0 - lse;
    out[g * 2 + 1] = l1 - lse;
}

// ---------------- launch ----------------
extern "C" void kernel_launch(void* const* d_in, const int* in_sizes, int n_in,
                              void* d_out, int out_size) {
    const float* x        = (const float*)d_in[0];
    const float* edge_attr= (const float*)d_in[1];
    const float* lin0_w   = (const float*)d_in[2];
    const float* lin0_b   = (const float*)d_in[3];
    const float* nn_w     = (const float*)d_in[4];
    const float* nn_b     = (const float*)d_in[5];
    const float* root_w   = (const float*)d_in[6];
    const float* conv_b   = (const float*)d_in[7];
    const float* gru_wi   = (const float*)d_in[8];
    const float* gru_wh   = (const float*)d_in[9];
    const float* gru_bi   = (const float*)d_in[10];
    const float* gru_bh   = (const float*)d_in[11];
    const float* lin1_w   = (const float*)d_in[12];
    const float* lin1_b   = (const float*)d_in[13];
    const int*   edge_idx = (const int*)d_in[14];
    const int*   batch    = (const int*)d_in[15];
    float* out = (float*)d_out;

    const int TPB = 256;
    const int nodeBlocks = (NN + 31) / 32;                 // 1563
    const int edgeWarpBlocks = (EE * 32 + TPB - 1) / TPB;  // 12500
    const int packBlocks = (GG * DD + TPB - 1) / TPB;      // 256 (covers 12288 pack too)

    k_pack<<<packBlocks, TPB>>>(root_w, gru_wi, gru_wh, nn_w, nn_b);
    k_init<<<nodeBlocks, TPB>>>(x, lin0_w, lin0_b);

    for (int round = 0; round < 3; round++) {
        k_edge<<<edgeWarpBlocks, TPB>>>(edge_idx, edge_attr);
        k_node<<<nodeBlocks, TPB>>>(conv_b, gru_bi, gru_bh, batch, round == 2);
    }

    k_final<<<(GG + TPB - 1) / TPB, TPB>>>(lin1_w, lin1_b, out);
}